// round 5
// baseline (speedup 1.0000x reference)
#include <cuda_runtime.h>
#include <cuda_fp16.h>

#define NN 50000
#define FF 16
#define EE 800000
#define HH 64
#define TOUT 10
#define NF (NN*FF)
#define NBLK 148
#define NTHR 1024
#define NWARPS (NBLK*32)   // 4736
#define NSTAGE 240
#define NBIN 1024

// ---------------- device state ----------------
__device__ float   g_x0[NF];
__device__ float   g_xi[NF];
__device__ float   g_k[6][NF];
__device__ __half2 g_uv[2][NN*32];   // packed u, double-buffered
__device__ float   g_v[NN*HH];
__device__ float   g_augproj[NN*HH];
__device__ float   g_ys[TOUT*NF];
__device__ int     g_deg[NN];
__device__ int     g_rowptr[NN+1];
__device__ int     g_wptr[NN];
__device__ int     g_src_sorted[EE];
__device__ float4  g_ea_sorted[EE];
__device__ int     g_dbin[NBIN];
__device__ int     g_dwptr[NBIN];
__device__ int     g_nodes_sorted[NN];
__device__ unsigned g_arrive;

// DOPRI5 coefficients. Row 0 unused, rows 1..5 = A[0..4], row 6 = B.
__constant__ float c_coef[7][6] = {
  {0.f,0.f,0.f,0.f,0.f,0.f},
  {(float)(0.2), 0.f,0.f,0.f,0.f,0.f},
  {(float)(3.0/40.0), (float)(9.0/40.0), 0.f,0.f,0.f,0.f},
  {(float)(44.0/45.0), (float)(-56.0/15.0), (float)(32.0/9.0), 0.f,0.f,0.f},
  {(float)(19372.0/6561.0), (float)(-25360.0/2187.0), (float)(64448.0/6561.0), (float)(-212.0/729.0), 0.f,0.f},
  {(float)(9017.0/3168.0), (float)(-355.0/33.0), (float)(46732.0/5247.0), (float)(49.0/176.0), (float)(-5103.0/18656.0), 0.f},
  {(float)(35.0/384.0), 0.f, (float)(500.0/1113.0), (float)(125.0/192.0), (float)(-2187.0/6784.0), (float)(11.0/84.0)}
};
__constant__ float c_C[6] = {0.f, 0.2f, 0.3f, 0.8f, (float)(8.0/9.0), 1.f};

__device__ __forceinline__ float tanha(float x) {
  float r;
  asm("tanh.approx.f32 %0, %1;" : "=f"(r) : "f"(x));
  return r;
}

// ---------------- once-per-launch setup ----------------

__global__ __launch_bounds__(256) void augproj_kernel(
    const float* __restrict__ xh, const float* __restrict__ xm,
    const float* __restrict__ W1n, const float* __restrict__ b1n)
{
  __shared__ float saug[4][176];
  int tid = threadIdx.x;
  int ln = tid >> 6;
  int ch = tid & 63;
  int n = blockIdx.x * 4 + ln;
  if (ch < 16) {
    int f = ch;
    float xs[10], ms[10];
    float sm = 0.f, cm = 0.f;
    #pragma unroll
    for (int tt = 0; tt < 10; tt++) {
      xs[tt] = xh[(tt * NN + n) * FF + f];
      ms[tt] = xm[tt * NN + n];
      sm += xs[tt] * ms[tt];
      cm += ms[tt];
    }
    float cnt = fmaxf(cm, 1.0f);
    float mean = sm / cnt;
    float var = 0.f;
    #pragma unroll
    for (int tt = 0; tt < 10; tt++) { float d = xs[tt] - mean; var += d * d * ms[tt]; }
    var /= cnt;
    #pragma unroll
    for (int tt = 0; tt < 9; tt++)
      saug[ln][tt * 16 + f] = (xs[tt + 1] - xs[tt]) * (ms[tt + 1] * ms[tt]);
    saug[ln][144 + f] = mean;
    saug[ln][160 + f] = var;
  }
  __syncthreads();
  float acc = b1n[ch];
  #pragma unroll 8
  for (int r = 0; r < 176; r++)
    acc += saug[ln][r] * W1n[(32 + r) * 64 + ch];
  g_augproj[n * 64 + ch] = acc;
}

__global__ __launch_bounds__(256) void zero_kernel() {
  int i = blockIdx.x * 256 + threadIdx.x;
  if (i < NN) g_deg[i] = 0;
  if (i < NBIN) g_dbin[i] = 0;
  if (i == 0) g_arrive = 0u;
}

__global__ __launch_bounds__(256) void hist_kernel(const int* __restrict__ ei) {
  int e = blockIdx.x * 256 + threadIdx.x;
  if (e < EE) atomicAdd(&g_deg[ei[EE + e]], 1);
}

__global__ __launch_bounds__(1024) void scan_kernel() {
  __shared__ int wsum[32];
  int tid = threadIdx.x, lane = tid & 31, wid = tid >> 5;
  int carry = 0;
  for (int base = 0; base < NN; base += 1024) {
    int i = base + tid;
    int v = (i < NN) ? g_deg[i] : 0;
    int x = v;
    #pragma unroll
    for (int o = 1; o < 32; o <<= 1) { int y = __shfl_up_sync(0xffffffffu, x, o); if (lane >= o) x += y; }
    if (lane == 31) wsum[wid] = x;
    __syncthreads();
    if (wid == 0) {
      int s = wsum[lane];
      #pragma unroll
      for (int o = 1; o < 32; o <<= 1) { int y = __shfl_up_sync(0xffffffffu, s, o); if (lane >= o) s += y; }
      wsum[lane] = s;
    }
    __syncthreads();
    int incl = x + carry + (wid > 0 ? wsum[wid - 1] : 0);
    if (i < NN) { g_rowptr[i + 1] = incl; g_wptr[i] = incl - v; }
    carry += wsum[31];
    __syncthreads();
  }
  if (tid == 0) g_rowptr[0] = 0;
}

__global__ __launch_bounds__(256) void scatter_kernel(
    const int* __restrict__ ei, const float* __restrict__ ea)
{
  int e = blockIdx.x * 256 + threadIdx.x;
  if (e < EE) {
    int d = ei[EE + e];
    int pos = atomicAdd(&g_wptr[d], 1);
    g_src_sorted[pos] = ei[e];
    g_ea_sorted[pos] = ((const float4*)ea)[e];
  }
}

// degree histogram (descending order bins) for balanced node assignment
__global__ __launch_bounds__(256) void dhist_kernel() {
  int n = blockIdx.x * 256 + threadIdx.x;
  if (n < NN) {
    int d = g_deg[n]; if (d > NBIN - 1) d = NBIN - 1;
    atomicAdd(&g_dbin[(NBIN - 1) - d], 1);
  }
}

__global__ __launch_bounds__(1024) void dscan_kernel() {
  __shared__ int wsum[32];
  int tid = threadIdx.x, lane = tid & 31, wid = tid >> 5;
  int v = g_dbin[tid];
  int x = v;
  #pragma unroll
  for (int o = 1; o < 32; o <<= 1) { int y = __shfl_up_sync(0xffffffffu, x, o); if (lane >= o) x += y; }
  if (lane == 31) wsum[wid] = x;
  __syncthreads();
  if (wid == 0) {
    int s = wsum[lane];
    #pragma unroll
    for (int o = 1; o < 32; o <<= 1) { int y = __shfl_up_sync(0xffffffffu, s, o); if (lane >= o) s += y; }
    wsum[lane] = s;
  }
  __syncthreads();
  int incl = x + (wid > 0 ? wsum[wid - 1] : 0);
  g_dwptr[tid] = incl - v;   // exclusive
}

__global__ __launch_bounds__(256) void dscatter_kernel() {
  int n = blockIdx.x * 256 + threadIdx.x;
  if (n < NN) {
    int d = g_deg[n]; if (d > NBIN - 1) d = NBIN - 1;
    int pos = atomicAdd(&g_dwptr[(NBIN - 1) - d], 1);
    g_nodes_sorted[pos] = n;
  }
}

// initial state: x0 = x_hist[-1], xi = x0, u/v projections into buffer 0
__global__ __launch_bounds__(256) void init_kernel(
    const float* __restrict__ xh,
    const float* __restrict__ W1m, const float* __restrict__ b1m)
{
  __shared__ float sW[32 * 64];
  __shared__ float sb[64];
  __shared__ float sxi[8][16];
  int tid = threadIdx.x;
  #pragma unroll
  for (int i = tid; i < 512; i += 256) ((float4*)sW)[i] = ((const float4*)W1m)[i];
  if (tid < 16) ((float4*)sb)[tid] = ((const float4*)b1m)[tid];
  int w = tid >> 5, lane = tid & 31;
  int n = blockIdx.x * 8 + w;
  if (lane < 16) {
    int idx = n * 16 + lane;
    float xv = xh[9 * NF + idx];
    g_x0[idx] = xv;
    g_xi[idx] = xv;
    sxi[w][lane] = xv;
  }
  __syncthreads();
  float u0 = 0.f, u1 = 0.f;
  float v0 = sb[lane], v1 = sb[32 + lane];
  #pragma unroll
  for (int i = 0; i < 16; i++) {
    float xv = sxi[w][i];
    u0 += xv * sW[i * 64 + lane];
    u1 += xv * sW[i * 64 + 32 + lane];
    v0 += xv * sW[(16 + i) * 64 + lane];
    v1 += xv * sW[(16 + i) * 64 + 32 + lane];
  }
  g_uv[0][n * 32 + lane] = __floats2half2_rn(u0, u1);
  g_v[n * 64 + lane] = v0;
  g_v[n * 64 + 32 + lane] = v1;
}

// ---------------- persistent main kernel ----------------

__device__ __forceinline__ void gsync(int stage) {
  __syncthreads();
  if (threadIdx.x == 0) {
    __threadfence();                       // release: u/v stores visible
    atomicAdd(&g_arrive, 1u);
    unsigned target = (unsigned)NBLK * (unsigned)(stage + 1);
    while (*(volatile unsigned*)&g_arrive < target) __nanosleep(64);
    __threadfence();                       // acquire
  }
  __syncthreads();
}

__global__ __launch_bounds__(NTHR, 1) void ode_main(
    const float* __restrict__ t,
    const float* __restrict__ W1m, const float* __restrict__ W2m,
    const float* __restrict__ b2m, const float* __restrict__ W1n,
    const float* __restrict__ W2n, const float* __restrict__ b2n,
    const float* __restrict__ b1m)
{
  __shared__ float sWea[4 * 64];
  __shared__ float sW2m[64 * 16];
  __shared__ float sW1nx[16 * 64];
  __shared__ float sW1na[16 * 64];
  __shared__ float sW2n[64 * 16];
  __shared__ float sW1m[32 * 64];
  __shared__ float swt[64];
  __shared__ float sb1m[64];
  __shared__ float sb2m[16], sb2n[16];
  __shared__ float st[TOUT + 1];
  __shared__ float sbuf[32][64];
  __shared__ float sxi[32][16];
  __shared__ float sagg[32][16];
  __shared__ float sxin[32][16];

  int tid = threadIdx.x;
  // stage all weights once (vectorized)
  if (tid < 64)  ((float4*)sWea)[tid] = ((const float4*)(W1m + 32 * 64))[tid];
  if (tid >= 64 && tid < 320)   ((float4*)sW2m)[tid - 64]   = ((const float4*)W2m)[tid - 64];
  if (tid >= 320 && tid < 576)  ((float4*)sW1nx)[tid - 320] = ((const float4*)W1n)[tid - 320];
  if (tid >= 576 && tid < 832)  ((float4*)sW1na)[tid - 576] = ((const float4*)(W1n + 1024))[tid - 576];
  if (tid >= 832 && tid < 1088 - 64) ((float4*)sW2n)[tid - 832] = ((const float4*)W2n)[tid - 832];
  // remaining pieces
  {
    int r = tid - (1088 - 64); // 1024-64=960..1023 -> 0..63 unused; do explicit loops instead
  }
  for (int i = tid; i < 256; i += NTHR) ((float4*)sW2n)[i] = ((const float4*)W2n)[i];
  for (int i = tid; i < 512; i += NTHR) ((float4*)sW1m)[i] = ((const float4*)W1m)[i];
  if (tid < 16) ((float4*)swt)[tid]  = ((const float4*)(W1n + 208 * 64))[tid];
  if (tid >= 16 && tid < 32) ((float4*)sb1m)[tid - 16] = ((const float4*)b1m)[tid - 16];
  if (tid >= 32 && tid < 36) ((float4*)sb2m)[tid - 32] = ((const float4*)b2m)[tid - 32];
  if (tid >= 36 && tid < 40) ((float4*)sb2n)[tid - 36] = ((const float4*)b2n)[tid - 36];
  if (tid >= 40 && tid < 40 + TOUT + 1) st[tid - 40] = t[tid - 40];
  __syncthreads();

  int w = tid >> 5, lane = tid & 31;
  int gw = blockIdx.x * 32 + w;
  int j = lane & 15;
  int cbase = (lane < 16) ? 0 : 32;

  // edge-layer weights held in registers for the whole kernel
  float wx0 = sWea[lane],        wx1 = sWea[32 + lane];
  float wy0 = sWea[64 + lane],   wy1 = sWea[96 + lane];
  float wz0 = sWea[128 + lane],  wz1 = sWea[160 + lane];
  float ww0 = sWea[192 + lane],  ww1 = sWea[224 + lane];

  for (int L = 0; L < NSTAGE; L++) {
    int s = L % 6;
    int sub = (L / 6) & 3;
    int it = L / 24;
    int pb = L & 1;
    float tA = st[it], tB = st[it + 1];
    float dti = (tB - tA) * 0.25f;
    float ti = tA + (float)sub * dti + c_C[s] * dti;
    int outrow = (s == 5 && sub == 3) ? it : -1;
    int krow = (s < 5) ? s + 1 : 6;

    const unsigned* __restrict__ U = (const unsigned*)&g_uv[pb][0];

    for (int ni = gw; ni < NN; ni += NWARPS) {
      int n = g_nodes_sorted[ni];

      if (lane < 16) sxi[w][lane] = g_xi[n * 16 + lane];
      __syncwarp();

      float v0 = g_v[n * 64 + lane];
      float v1 = g_v[n * 64 + 32 + lane];

      float acc0 = 0.f, acc1 = 0.f;
      int beg = g_rowptr[n], end = g_rowptr[n + 1];

      // 2-deep software pipeline; u via L1-bypass (cross-SM coherence)
      int e = beg;
      int srcc = 0; float4 eac = make_float4(0.f, 0.f, 0.f, 0.f); unsigned uhc = 0u;
      if (e < end) {
        srcc = g_src_sorted[e];
        eac  = g_ea_sorted[e];
        uhc  = __ldcg(U + srcc * 32 + lane);
      }
      for (; e < end; e++) {
        int e1 = e + 1;
        float4 ean = eac; unsigned uhn = uhc;
        if (e1 < end) {
          int srcn = g_src_sorted[e1];
          ean = g_ea_sorted[e1];
          uhn = __ldcg(U + srcn * 32 + lane);
        }
        __half2 h2 = *reinterpret_cast<__half2*>(&uhc);
        float2 uf = __half22float2(h2);
        float a0 = uf.x + v0;
        float a1 = uf.y + v1;
        a0 += eac.x * wx0 + eac.y * wy0 + eac.z * wz0 + eac.w * ww0;
        a1 += eac.x * wx1 + eac.y * wy1 + eac.z * wz1 + eac.w * ww1;
        acc0 += tanha(a0);
        acc1 += tanha(a1);
        eac = ean; uhc = uhn;
      }

      // agg16 = hsum @ W2m + deg*b2m
      sbuf[w][lane] = acc0;
      sbuf[w][32 + lane] = acc1;
      __syncwarp();
      float p = 0.f;
      #pragma unroll
      for (int c = 0; c < 32; c++) p += sbuf[w][cbase + c] * sW2m[(cbase + c) * 16 + j];
      p += __shfl_xor_sync(0xffffffffu, p, 16);
      float degf = (float)(end - beg);
      if (lane < 16) sagg[w][lane] = p + degf * sb2m[j];
      __syncwarp();

      // hidden = xi@W1n_x + agg@W1n_agg + aug_proj + ti*wt
      float h0 = g_augproj[n * 64 + lane]      + ti * swt[lane];
      float h1 = g_augproj[n * 64 + 32 + lane] + ti * swt[32 + lane];
      #pragma unroll
      for (int i = 0; i < 16; i++) {
        float xv = sxi[w][i], av = sagg[w][i];
        h0 += xv * sW1nx[i * 64 + lane]      + av * sW1na[i * 64 + lane];
        h1 += xv * sW1nx[i * 64 + 32 + lane] + av * sW1na[i * 64 + 32 + lane];
      }
      __syncwarp();
      sbuf[w][lane] = tanha(h0);
      sbuf[w][32 + lane] = tanha(h1);
      __syncwarp();

      float o = 0.f;
      #pragma unroll
      for (int c = 0; c < 32; c++) o += sbuf[w][cbase + c] * sW2n[(cbase + c) * 16 + j];
      o += __shfl_xor_sync(0xffffffffu, o, 16);
      float kval = o + sb2n[j];

      // epilogue: k store, xi_{s+1} combine, u/v projection into buffer pb^1
      if (lane < 16) {
        int idx = n * 16 + j;
        g_k[s][idx] = kval;
        float acc = c_coef[krow][s] * kval;
        #pragma unroll
        for (int jj = 0; jj < 5; jj++) {
          if (jj < s) acc += c_coef[krow][jj] * g_k[jj][idx];
        }
        float xv = g_x0[idx] + dti * acc;
        if (s == 5) {
          g_x0[idx] = xv;
          if (outrow >= 0) g_ys[outrow * NF + idx] = xv;
        }
        g_xi[idx] = xv;
        sxin[w][j] = xv;
      }
      __syncwarp();

      float u0 = 0.f, u1 = 0.f;
      float nv0 = sb1m[lane], nv1 = sb1m[32 + lane];
      #pragma unroll
      for (int i = 0; i < 16; i++) {
        float xv = sxin[w][i];
        u0  += xv * sW1m[i * 64 + lane];
        u1  += xv * sW1m[i * 64 + 32 + lane];
        nv0 += xv * sW1m[(16 + i) * 64 + lane];
        nv1 += xv * sW1m[(16 + i) * 64 + 32 + lane];
      }
      g_uv[pb ^ 1][n * 32 + lane] = __floats2half2_rn(u0, u1);
      g_v[n * 64 + lane] = nv0;
      g_v[n * 64 + 32 + lane] = nv1;
    }

    gsync(L);
  }
}

__global__ __launch_bounds__(256) void gather_out_kernel(
    const int* __restrict__ mask_idx, float* __restrict__ out)
{
  int idx = blockIdx.x * 256 + threadIdx.x;
  if (idx < TOUT * NF) {
    int row = idx / NF;
    int rem = idx - row * NF;
    out[idx] = g_ys[mask_idx[row] * NF + rem];
  }
}

// ---------------- launcher ----------------
extern "C" void kernel_launch(void* const* d_in, const int* in_sizes, int n_in,
                              void* d_out, int out_size)
{
  const float* x_hist   = (const float*)d_in[0];
  const float* x_mask   = (const float*)d_in[1];
  const int*   ei       = (const int*)d_in[2];
  const float* ea       = (const float*)d_in[3];
  const float* t        = (const float*)d_in[4];
  const int*   mask_idx = (const int*)d_in[5];
  const float* W1m = (const float*)d_in[6];
  const float* b1m = (const float*)d_in[7];
  const float* W2m = (const float*)d_in[8];
  const float* b2m = (const float*)d_in[9];
  const float* W1n = (const float*)d_in[10];
  const float* b1n = (const float*)d_in[11];
  const float* W2n = (const float*)d_in[12];
  const float* b2n = (const float*)d_in[13];
  float* out = (float*)d_out;

  // once-per-launch preprocessing
  augproj_kernel<<<NN / 4, 256>>>(x_hist, x_mask, W1n, b1n);
  zero_kernel<<<(NN + 255) / 256, 256>>>();
  hist_kernel<<<(EE + 255) / 256, 256>>>(ei);
  scan_kernel<<<1, 1024>>>();
  scatter_kernel<<<(EE + 255) / 256, 256>>>(ei, ea);
  dhist_kernel<<<(NN + 255) / 256, 256>>>();
  dscan_kernel<<<1, 1024>>>();
  dscatter_kernel<<<(NN + 255) / 256, 256>>>();
  init_kernel<<<NN / 8, 256>>>(x_hist, W1m, b1m);

  // all 240 RK stages in one persistent kernel
  ode_main<<<NBLK, NTHR>>>(t, W1m, W2m, b2m, W1n, W2n, b2n, b1m);

  gather_out_kernel<<<(TOUT * NF + 255) / 256, 256>>>(mask_idx, out);
}